// round 2
// baseline (speedup 1.0000x reference)
#include <cuda_runtime.h>

#define EXTENT 7
#define NBOX   1024
#define CH     256
#define NSAMP  (EXTENT * EXTENT)

__global__ __launch_bounds__(256, 4)
void roi_align_pyramid_kernel(
    const float* __restrict__ metadata,
    const float* __restrict__ boxes,
    const float* __restrict__ p2,
    const float* __restrict__ p3,
    const float* __restrict__ p4,
    const float* __restrict__ p5,
    float* __restrict__ out)
{
    const int box = blockIdx.x;
    const int tid = threadIdx.x;      // 0..255
    const int tx  = tid & 63;         // float4 channel group (64 * 4 = 256 ch)
    const int ty  = tid >> 6;         // sample lane 0..3

    const float rows = metadata[0];
    const float cols = metadata[1];

    const float x1 = boxes[box * 4 + 0];
    const float y1 = boxes[box * 4 + 1];
    const float x2 = boxes[box * 4 + 2];
    const float y2 = boxes[box * 4 + 3];

    const float h = y2 - y1;
    const float w = x2 - x1;

    // roi_level = min(5, max(2, 4 + round(log(sqrt(h*w)/sqrt(rows*cols)) / log(2))))
    // rintf = round-half-to-even, matching jnp.round.
    const float roi  = logf(sqrtf(h * w) / sqrtf(rows * cols)) * (1.0f / logf(2.0f));
    const float lvlf = fminf(5.0f, fmaxf(2.0f, 4.0f + rintf(roi)));
    const int   lvl  = (int)lvlf;

    const float* feat;
    int H;
    switch (lvl) {
        case 2:  feat = p2; H = 256; break;
        case 3:  feat = p3; H = 128; break;
        case 4:  feat = p4; H = 64;  break;
        default: feat = p5; H = 32;  break;
    }
    const int W = H;

    __shared__ int   y0s[EXTENT], x0s[EXTENT];
    __shared__ float wys[EXTENT], wxs[EXTENT];

    if (tid < EXTENT) {
        const float g   = (float)tid / (float)(EXTENT - 1);
        const float ny1 = y1 / (rows - 1.0f);
        const float ny2 = y2 / (rows - 1.0f);
        const float nx1 = x1 / (cols - 1.0f);
        const float nx2 = x2 / (cols - 1.0f);
        const float ysv = (ny1 + (ny2 - ny1) * g) * (float)(H - 1);
        const float xsv = (nx1 + (nx2 - nx1) * g) * (float)(W - 1);
        const float y0f = fminf(fmaxf(floorf(ysv), 0.0f), (float)(H - 2));
        const float x0f = fminf(fmaxf(floorf(xsv), 0.0f), (float)(W - 2));
        y0s[tid] = (int)y0f;
        x0s[tid] = (int)x0f;
        wys[tid] = ysv - y0f;
        wxs[tid] = xsv - x0f;
    }
    __syncthreads();

    const float4* __restrict__ f4 = (const float4*)feat;
    float4* __restrict__ o4 = (float4*)out;
    const int cvec = CH / 4;   // 64 float4 per pixel

    for (int s = ty; s < NSAMP; s += 4) {
        const int gy = s / EXTENT;
        const int gx = s - gy * EXTENT;
        const int y0 = y0s[gy];
        const int x0 = x0s[gx];
        const float wy = wys[gy];
        const float wx = wxs[gx];

        const int base00 = (y0 * W + x0) * cvec + tx;
        const float4 a = f4[base00];                 // (y0,   x0)
        const float4 b = f4[base00 + cvec];          // (y0,   x0+1)
        const float4 c = f4[base00 + W * cvec];      // (y0+1, x0)
        const float4 d = f4[base00 + W * cvec + cvec]; // (y0+1, x0+1)

        const float w00 = (1.0f - wy) * (1.0f - wx);
        const float w01 = (1.0f - wy) * wx;
        const float w10 = wy * (1.0f - wx);
        const float w11 = wy * wx;

        float4 r;
        r.x = a.x * w00 + b.x * w01 + c.x * w10 + d.x * w11;
        r.y = a.y * w00 + b.y * w01 + c.y * w10 + d.y * w11;
        r.z = a.z * w00 + b.z * w01 + c.z * w10 + d.z * w11;
        r.w = a.w * w00 + b.w * w01 + c.w * w10 + d.w * w11;

        o4[(box * NSAMP + s) * cvec + tx] = r;
    }
}

extern "C" void kernel_launch(void* const* d_in, const int* in_sizes, int n_in,
                              void* d_out, int out_size) {
    const float* metadata = (const float*)d_in[0];
    const float* boxes    = (const float*)d_in[1];
    const float* p2       = (const float*)d_in[2];
    const float* p3       = (const float*)d_in[3];
    const float* p4       = (const float*)d_in[4];
    const float* p5       = (const float*)d_in[5];
    float* out = (float*)d_out;

    roi_align_pyramid_kernel<<<NBOX, 256>>>(metadata, boxes, p2, p3, p4, p5, out);
}

// round 3
// speedup vs baseline: 1.1620x; 1.1620x over previous
#include <cuda_runtime.h>

#define EXTENT 7
#define NBOX   1024
#define CH     256
#define NSAMP  (EXTENT * EXTENT)

__device__ __forceinline__ void stcs4(float4* p, float4 v) {
    asm volatile("st.global.cs.v4.f32 [%0], {%1,%2,%3,%4};"
                 :: "l"(p), "f"(v.x), "f"(v.y), "f"(v.z), "f"(v.w) : "memory");
}

__global__ __launch_bounds__(256)
void roi_align_pyramid_kernel(
    const float* __restrict__ metadata,
    const float* __restrict__ boxes,
    const float* __restrict__ p2,
    const float* __restrict__ p3,
    const float* __restrict__ p4,
    const float* __restrict__ p5,
    float* __restrict__ out)
{
    const int box = blockIdx.x;
    const int tid = threadIdx.x;      // 0..255
    const int tx  = tid & 63;         // float4 channel group (64 * 4 = 256 ch)
    const int ty  = tid >> 6;         // sample lane 0..3

    const float rows = metadata[0];
    const float cols = metadata[1];

    const float x1 = boxes[box * 4 + 0];
    const float y1 = boxes[box * 4 + 1];
    const float x2 = boxes[box * 4 + 2];
    const float y2 = boxes[box * 4 + 3];

    const float h = y2 - y1;
    const float w = x2 - x1;

    // roi_level = min(5, max(2, 4 + round(log(sqrt(h*w)/sqrt(rows*cols)) / log(2))))
    // rintf = round-half-to-even, matching jnp.round.
    const float roi  = logf(sqrtf(h * w) / sqrtf(rows * cols)) * (1.0f / logf(2.0f));
    const float lvlf = fminf(5.0f, fmaxf(2.0f, 4.0f + rintf(roi)));
    const int   lvl  = (int)lvlf;

    const float* feat;
    int H;
    switch (lvl) {
        case 2:  feat = p2; H = 256; break;
        case 3:  feat = p3; H = 128; break;
        case 4:  feat = p4; H = 64;  break;
        default: feat = p5; H = 32;  break;
    }
    const int W = H;

    __shared__ int   y0s[EXTENT], x0s[EXTENT];
    __shared__ float wys[EXTENT], wxs[EXTENT];

    if (tid < EXTENT) {
        const float g   = (float)tid / (float)(EXTENT - 1);
        const float ny1 = y1 / (rows - 1.0f);
        const float ny2 = y2 / (rows - 1.0f);
        const float nx1 = x1 / (cols - 1.0f);
        const float nx2 = x2 / (cols - 1.0f);
        const float ysv = (ny1 + (ny2 - ny1) * g) * (float)(H - 1);
        const float xsv = (nx1 + (nx2 - nx1) * g) * (float)(W - 1);
        const float y0f = fminf(fmaxf(floorf(ysv), 0.0f), (float)(H - 2));
        const float x0f = fminf(fmaxf(floorf(xsv), 0.0f), (float)(W - 2));
        y0s[tid] = (int)y0f;
        x0s[tid] = (int)x0f;
        wys[tid] = ysv - y0f;
        wxs[tid] = xsv - x0f;
    }
    __syncthreads();

    const float4* __restrict__ f4 = (const float4*)feat;
    float4* __restrict__ o4 = (float4*)out;
    const int cvec = CH / 4;   // 64 float4 per pixel
    const int wrow = W * cvec;

    // Process two samples per iteration: 8 independent loads in flight.
    int s = ty;
    #pragma unroll 1
    for (; s + 4 < NSAMP; s += 8) {
        const int sA = s, sB = s + 4;
        const int gyA = sA / EXTENT, gxA = sA - gyA * EXTENT;
        const int gyB = sB / EXTENT, gxB = sB - gyB * EXTENT;

        const int baseA = (y0s[gyA] * W + x0s[gxA]) * cvec + tx;
        const int baseB = (y0s[gyB] * W + x0s[gxB]) * cvec + tx;

        const float4 a0 = f4[baseA];
        const float4 b0 = f4[baseA + cvec];
        const float4 c0 = f4[baseA + wrow];
        const float4 d0 = f4[baseA + wrow + cvec];
        const float4 a1 = f4[baseB];
        const float4 b1 = f4[baseB + cvec];
        const float4 c1 = f4[baseB + wrow];
        const float4 d1 = f4[baseB + wrow + cvec];

        const float wyA = wys[gyA], wxA = wxs[gxA];
        const float wyB = wys[gyB], wxB = wxs[gxB];

        const float w00A = (1.0f - wyA) * (1.0f - wxA);
        const float w01A = (1.0f - wyA) * wxA;
        const float w10A = wyA * (1.0f - wxA);
        const float w11A = wyA * wxA;
        const float w00B = (1.0f - wyB) * (1.0f - wxB);
        const float w01B = (1.0f - wyB) * wxB;
        const float w10B = wyB * (1.0f - wxB);
        const float w11B = wyB * wxB;

        float4 rA, rB;
        rA.x = a0.x * w00A + b0.x * w01A + c0.x * w10A + d0.x * w11A;
        rA.y = a0.y * w00A + b0.y * w01A + c0.y * w10A + d0.y * w11A;
        rA.z = a0.z * w00A + b0.z * w01A + c0.z * w10A + d0.z * w11A;
        rA.w = a0.w * w00A + b0.w * w01A + c0.w * w10A + d0.w * w11A;
        rB.x = a1.x * w00B + b1.x * w01B + c1.x * w10B + d1.x * w11B;
        rB.y = a1.y * w00B + b1.y * w01B + c1.y * w10B + d1.y * w11B;
        rB.z = a1.z * w00B + b1.z * w01B + c1.z * w10B + d1.z * w11B;
        rB.w = a1.w * w00B + b1.w * w01B + c1.w * w10B + d1.w * w11B;

        stcs4(&o4[(box * NSAMP + sA) * cvec + tx], rA);
        stcs4(&o4[(box * NSAMP + sB) * cvec + tx], rB);
    }
    if (s < NSAMP) {
        const int gy = s / EXTENT;
        const int gx = s - gy * EXTENT;
        const int base00 = (y0s[gy] * W + x0s[gx]) * cvec + tx;
        const float4 a = f4[base00];
        const float4 b = f4[base00 + cvec];
        const float4 c = f4[base00 + wrow];
        const float4 d = f4[base00 + wrow + cvec];
        const float wy = wys[gy], wx = wxs[gx];
        const float w00 = (1.0f - wy) * (1.0f - wx);
        const float w01 = (1.0f - wy) * wx;
        const float w10 = wy * (1.0f - wx);
        const float w11 = wy * wx;
        float4 r;
        r.x = a.x * w00 + b.x * w01 + c.x * w10 + d.x * w11;
        r.y = a.y * w00 + b.y * w01 + c.y * w10 + d.y * w11;
        r.z = a.z * w00 + b.z * w01 + c.z * w10 + d.z * w11;
        r.w = a.w * w00 + b.w * w01 + c.w * w10 + d.w * w11;
        stcs4(&o4[(box * NSAMP + s) * cvec + tx], r);
    }
}

extern "C" void kernel_launch(void* const* d_in, const int* in_sizes, int n_in,
                              void* d_out, int out_size) {
    const float* metadata = (const float*)d_in[0];
    const float* boxes    = (const float*)d_in[1];
    const float* p2       = (const float*)d_in[2];
    const float* p3       = (const float*)d_in[3];
    const float* p4       = (const float*)d_in[4];
    const float* p5       = (const float*)d_in[5];
    float* out = (float*)d_out;

    roi_align_pyramid_kernel<<<NBOX, 256>>>(metadata, boxes, p2, p3, p4, p5, out);
}